// round 3
// baseline (speedup 1.0000x reference)
#include <cuda_runtime.h>

#define F_ 256
#define T_ 128
#define D_ 6
#define U_ 16
#define NB_ 64
#define N_ 768          // T_*D_
#define BROWS 32        // batch rows per CTA
#define CCOLS 192       // 32 trees * 6 cols per chunk
#define NCHUNK 4
#define THREADS 512
#define SEL_LD 196      // padded row stride for sel tile (floats)
#define P_LD 197        // padded row stride for p tile
#define RESP_LD 68      // padded row stride for response tile

// Selector matrix after sparsemax, stored K-major: g_sel[f*768 + t*6 + d]
__device__ float g_sel[F_ * N_];

typedef unsigned long long u64;

__device__ __forceinline__ float f4get(const float4& v, int i) {
    return i == 0 ? v.x : (i == 1 ? v.y : (i == 2 ? v.z : v.w));
}
__device__ __forceinline__ u64 pk(float lo, float hi) {
    u64 r; asm("mov.b64 %0, {%1, %2};" : "=l"(r) : "f"(lo), "f"(hi)); return r;
}
__device__ __forceinline__ u64 pkdup(float v) { return pk(v, v); }
__device__ __forceinline__ u64 mul2(u64 a, u64 b) {
    u64 d; asm("mul.rn.f32x2 %0, %1, %2;" : "=l"(d) : "l"(a), "l"(b)); return d;
}
__device__ __forceinline__ u64 fma2(u64 a, u64 b, u64 c) {
    u64 d; asm("fma.rn.f32x2 %0, %1, %2, %3;" : "=l"(d) : "l"(a), "l"(b), "l"(c)); return d;
}
__device__ __forceinline__ float lo32(u64 v) { return __uint_as_float((unsigned)(v & 0xffffffffull)); }
__device__ __forceinline__ float hi32(u64 v) { return __uint_as_float((unsigned)(v >> 32)); }

// ---------------------------------------------------------------------------
// Kernel 1: sparsemax over the last axis (D=6) of feature_selection_logits.
// ---------------------------------------------------------------------------
__global__ __launch_bounds__(256) void sparsemax_kernel(const float* __restrict__ fsl) {
    int idx = blockIdx.x * blockDim.x + threadIdx.x;   // 0 .. F_*T_-1
    if (idx >= F_ * T_) return;
    const float* zin = fsl + (size_t)idx * D_;
    float z[D_], zs[D_];
#pragma unroll
    for (int d = 0; d < D_; d++) { z[d] = zin[d]; zs[d] = z[d]; }
#pragma unroll
    for (int i = 0; i < D_; i++) {
#pragma unroll
        for (int j = 0; j < D_ - 1; j++) {
            if (zs[j] < zs[j + 1]) { float t = zs[j]; zs[j] = zs[j + 1]; zs[j + 1] = t; }
        }
    }
    float csum[D_];
    float cs = 0.0f;
#pragma unroll
    for (int k = 0; k < D_; k++) { cs += zs[k]; csum[k] = cs; }
    int kz = 0;
#pragma unroll
    for (int k = 0; k < D_; k++) {
        if (1.0f + (float)(k + 1) * zs[k] > csum[k]) kz++;
    }
    float tau = (csum[kz - 1] - 1.0f) / (float)kz;
    float* outp = g_sel + (size_t)idx * D_;
#pragma unroll
    for (int d = 0; d < D_; d++) outp[d] = fmaxf(z[d] - tau, 0.0f);
}

// ---------------------------------------------------------------------------
// Kernel 2: fused feature GEMM + sparsemoid + tree eval + response contraction.
// 512 threads, 32 batch rows/CTA, 4 chunks of 32 trees. Eval uses f32x2 FFMA2.
// ---------------------------------------------------------------------------
__global__ __launch_bounds__(THREADS, 1) void odst_main(
    const float* __restrict__ x,
    const float* __restrict__ thr,
    const float* __restrict__ lt,
    const float* __restrict__ resp,
    float* __restrict__ out)
{
    extern __shared__ float smem[];
    float* x_s    = smem;                        // [32][256]        8192 f
    float* sel_s  = x_s + 32 * 256;              // [64][SEL_LD]    12544 f
    float* p_s    = sel_s + 64 * SEL_LD;         // [32][P_LD]       6304 f
    float* a_s    = p_s + 32 * P_LD;             // [192]
    float* b_s    = a_s + CCOLS;                 // [192]
    float* resp_s = b_s + CCOLS;                 // [16][16][RESP_LD] 17408 f
    float* out_s  = resp_s + 16 * 16 * RESP_LD;  // [32][16]          512 f

    const int tid  = threadIdx.x;
    const int row0 = blockIdx.x * BROWS;

    out_s[tid] = 0.0f;

    // load x tile (coalesced float4): 2048 float4 over 512 threads
    {
        const float4* xg = (const float4*)(x + (size_t)row0 * F_);
        float4* xs4 = (float4*)x_s;
#pragma unroll
        for (int i = 0; i < 4; i++) xs4[tid + i * 512] = xg[tid + i * 512];
    }

    // eval-phase decomposition: warp -> tree slot, lane -> (row quad, u quad)
    const int w    = tid >> 5;          // 0..15
    const int lane = tid & 31;
    const int rb   = (lane & 7) * 4;    // row base (4 rows)
    const int ub   = (lane >> 3) * 4;   // u base (4 outputs)

    // GEMM-phase decomposition: 8 row groups x 64 col groups, tile 4r x 3c
    const int colg = tid & 63;
    const int rowg = tid >> 6;          // 0..7
    const int c0   = colg * 3;
    const int r0g  = rowg * 4;

    // packed accumulators: pr pairs rows (rb+2pr, rb+2pr+1) in (lo, hi)
    u64 accp[2][4];
#pragma unroll
    for (int pr = 0; pr < 2; pr++)
#pragma unroll
        for (int uu = 0; uu < 4; uu++) accp[pr][uu] = 0ull;

    for (int chunk = 0; chunk < NCHUNK; chunk++) {
        const int nbase = chunk * CCOLS;
        __syncthreads();  // previous chunk's eval done; x_s loaded (1st iter)

        if (tid < CCOLS) {
            float e = 0.5f * expf(-lt[nbase + tid]);
            a_s[tid] = e;
            b_s[tid] = 0.5f - e * thr[nbase + tid];
        }

        float fv[4][3];
#pragma unroll
        for (int i = 0; i < 4; i++) { fv[i][0] = 0.f; fv[i][1] = 0.f; fv[i][2] = 0.f; }

        for (int kb = 0; kb < 4; kb++) {
            __syncthreads();
            // stage selector tile: 64 k-rows x 192 cols = 3072 float4
            const float* gs = g_sel + (size_t)(kb * 64) * N_ + nbase;
#pragma unroll
            for (int i = 0; i < 6; i++) {
                int q  = tid + i * 512;          // float4 index 0..3071
                int kk = q / 48;
                int cc = (q % 48) * 4;
                *(float4*)&sel_s[kk * SEL_LD + cc] = *(const float4*)&gs[kk * N_ + cc];
            }
            __syncthreads();

            const float* xrow = x_s + r0g * 256 + kb * 64;
#pragma unroll 4
            for (int k = 0; k < 64; k++) {
                const float* sr = sel_s + k * SEL_LD + c0;
                float s0 = sr[0], s1 = sr[1], s2 = sr[2];
#pragma unroll
                for (int i = 0; i < 4; i++) {
                    float xv = xrow[i * 256 + k];   // broadcast within warp
                    fv[i][0] = fmaf(xv, s0, fv[i][0]);
                    fv[i][1] = fmaf(xv, s1, fv[i][1]);
                    fv[i][2] = fmaf(xv, s2, fv[i][2]);
                }
            }
        }

        // sparsemoid: p = saturate(a*fv + b)
#pragma unroll
        for (int i = 0; i < 4; i++) {
#pragma unroll
            for (int j = 0; j < 3; j++) {
                int cc = c0 + j;
                p_s[(r0g + i) * P_LD + cc] =
                    __saturatef(fmaf(a_s[cc], fv[i][j], b_s[cc]));
            }
        }
        __syncthreads();

        // tree eval: warp w handles trees chunk*32 + {w, w+16}
        for (int it = 0; it < 2; it++) {
            const int tloc = it * 16 + w;
            const int tg   = chunk * 32 + tloc;
            float* rs = resp_s + w * (16 * RESP_LD);
            // warp-private response staging (16 u x 64 bins)
            {
                const float4* rg = (const float4*)(resp + (size_t)tg * (U_ * NB_));
#pragma unroll
                for (int m = 0; m < 8; m++) {
                    int q  = m * 32 + lane;   // float4 index 0..255
                    int u  = q >> 4;
                    int cq = q & 15;
                    *(float4*)&rs[u * RESP_LD + cq * 4] = rg[q];
                }
            }
            __syncwarp();

            const int pc = tloc * 6;
            // packed pairwise depth-product tables, rows paired (rb+2pr, rb+2pr+1)
            u64 r01p[2][4], r23p[2][4], r45p[2][4];
#pragma unroll
            for (int pr = 0; pr < 2; pr++) {
                const float* prow0 = p_s + (rb + 2 * pr) * P_LD + pc;
                const float* prow1 = prow0 + P_LD;   // adjacent row (FIX: was +2*P_LD)
                u64 P0 = pk(prow0[0], prow1[0]);
                u64 P1 = pk(prow0[1], prow1[1]);
                u64 P2 = pk(prow0[2], prow1[2]);
                u64 P3 = pk(prow0[3], prow1[3]);
                u64 P4 = pk(prow0[4], prow1[4]);
                u64 P5 = pk(prow0[5], prow1[5]);
                const u64 ONE = 0x3f8000003f800000ull;   // (1.0f, 1.0f)
                const u64 NEG = 0xbf800000bf800000ull;   // (-1.0f, -1.0f)
                u64 Q0 = fma2(P0, NEG, ONE);
                u64 Q1 = fma2(P1, NEG, ONE);
                u64 Q2 = fma2(P2, NEG, ONE);
                u64 Q3 = fma2(P3, NEG, ONE);
                u64 Q4 = fma2(P4, NEG, ONE);
                u64 Q5 = fma2(P5, NEG, ONE);
                // index j = b0 + 2*b1; bit==0 -> p, bit==1 -> 1-p
                r01p[pr][0] = mul2(P0, P1); r01p[pr][1] = mul2(Q0, P1);
                r01p[pr][2] = mul2(P0, Q1); r01p[pr][3] = mul2(Q0, Q1);
                r23p[pr][0] = mul2(P2, P3); r23p[pr][1] = mul2(Q2, P3);
                r23p[pr][2] = mul2(P2, Q3); r23p[pr][3] = mul2(Q2, Q3);
                r45p[pr][0] = mul2(P4, P5); r45p[pr][1] = mul2(Q4, P5);
                r45p[pr][2] = mul2(P4, Q5); r45p[pr][3] = mul2(Q4, Q5);
            }

#pragma unroll
            for (int j45 = 0; j45 < 4; j45++) {
#pragma unroll
                for (int j23 = 0; j23 < 4; j23++) {
                    u64 t2p0 = mul2(r45p[0][j45], r23p[0][j23]);
                    u64 t2p1 = mul2(r45p[1][j45], r23p[1][j23]);
                    const int cb = j45 * 16 + j23 * 4;
                    float4 rv0 = *(const float4*)&rs[(ub + 0) * RESP_LD + cb];
                    float4 rv1 = *(const float4*)&rs[(ub + 1) * RESP_LD + cb];
                    float4 rv2 = *(const float4*)&rs[(ub + 2) * RESP_LD + cb];
                    float4 rv3 = *(const float4*)&rs[(ub + 3) * RESP_LD + cb];
#pragma unroll
                    for (int j01 = 0; j01 < 4; j01++) {
                        u64 rw0 = mul2(t2p0, r01p[0][j01]);
                        u64 rw1 = mul2(t2p1, r01p[1][j01]);
                        u64 e0 = pkdup(f4get(rv0, j01));
                        u64 e1 = pkdup(f4get(rv1, j01));
                        u64 e2 = pkdup(f4get(rv2, j01));
                        u64 e3 = pkdup(f4get(rv3, j01));
                        accp[0][0] = fma2(rw0, e0, accp[0][0]);
                        accp[0][1] = fma2(rw0, e1, accp[0][1]);
                        accp[0][2] = fma2(rw0, e2, accp[0][2]);
                        accp[0][3] = fma2(rw0, e3, accp[0][3]);
                        accp[1][0] = fma2(rw1, e0, accp[1][0]);
                        accp[1][1] = fma2(rw1, e1, accp[1][1]);
                        accp[1][2] = fma2(rw1, e2, accp[1][2]);
                        accp[1][3] = fma2(rw1, e3, accp[1][3]);
                    }
                }
            }
            __syncwarp();   // protect rs before next iteration restages it
        }
    }

    // unpack accumulators into scalars
    float acc[4][4];
#pragma unroll
    for (int pr = 0; pr < 2; pr++)
#pragma unroll
        for (int uu = 0; uu < 4; uu++) {
            acc[2 * pr + 0][uu] = lo32(accp[pr][uu]);
            acc[2 * pr + 1][uu] = hi32(accp[pr][uu]);
        }

    // deterministic cross-warp reduction into out_s
    for (int pass = 0; pass < 16; pass++) {
        __syncthreads();
        if (w == pass) {
#pragma unroll
            for (int rr = 0; rr < 4; rr++)
#pragma unroll
                for (int uu = 0; uu < 4; uu++)
                    out_s[(rb + rr) * U_ + ub + uu] += acc[rr][uu];
        }
    }
    __syncthreads();

    // write output: 32 rows x 16 u = 512 floats, one per thread (coalesced)
    out[(size_t)row0 * U_ + tid] = out_s[tid];
}

// ---------------------------------------------------------------------------
extern "C" void kernel_launch(void* const* d_in, const int* in_sizes, int n_in,
                              void* d_out, int out_size) {
    const float* x    = (const float*)d_in[0];
    const float* fsl  = (const float*)d_in[1];
    const float* thr  = (const float*)d_in[2];
    const float* lt   = (const float*)d_in[3];
    const float* resp = (const float*)d_in[4];
    float* out = (float*)d_out;

    const int smem_bytes =
        (32 * 256 + 64 * SEL_LD + 32 * P_LD + 2 * CCOLS + 16 * 16 * RESP_LD + 512)
        * (int)sizeof(float);   // 181,376 B

    cudaFuncSetAttribute(odst_main, cudaFuncAttributeMaxDynamicSharedMemorySize,
                         smem_bytes);

    sparsemax_kernel<<<(F_ * T_) / 256, 256>>>(fsl);
    odst_main<<<(4096 / BROWS), THREADS, smem_bytes>>>(x, thr, lt, resp, out);
}

// round 4
// speedup vs baseline: 1.0812x; 1.0812x over previous
#include <cuda_runtime.h>

#define F_ 256
#define T_ 128
#define D_ 6
#define U_ 16
#define NB_ 64
#define N_ 768          // T_*D_
#define BROWS 32        // batch rows per CTA
#define CCOLS 192       // 32 trees * 6 cols per chunk
#define NCHUNK 4
#define THREADS 512
#define SEL_LD 196      // padded row stride for sel tile (floats)
#define P_LD 197        // padded row stride for p tile
#define XT_LD 36        // padded row stride for transposed x (floats, mult of 4)

// Selector matrix after sparsemax, stored K-major: g_sel[f*768 + t*6 + d]
__device__ float g_sel[F_ * N_];

typedef unsigned long long u64;

__device__ __forceinline__ float f4get(const float4& v, int i) {
    return i == 0 ? v.x : (i == 1 ? v.y : (i == 2 ? v.z : v.w));
}
__device__ __forceinline__ u64 pk(float lo, float hi) {
    u64 r; asm("mov.b64 %0, {%1, %2};" : "=l"(r) : "f"(lo), "f"(hi)); return r;
}
__device__ __forceinline__ u64 pkdup(float v) { return pk(v, v); }
__device__ __forceinline__ u64 mul2(u64 a, u64 b) {
    u64 d; asm("mul.rn.f32x2 %0, %1, %2;" : "=l"(d) : "l"(a), "l"(b)); return d;
}
__device__ __forceinline__ u64 fma2(u64 a, u64 b, u64 c) {
    u64 d; asm("fma.rn.f32x2 %0, %1, %2, %3;" : "=l"(d) : "l"(a), "l"(b), "l"(c)); return d;
}
__device__ __forceinline__ float lo32(u64 v) { return __uint_as_float((unsigned)(v & 0xffffffffull)); }
__device__ __forceinline__ float hi32(u64 v) { return __uint_as_float((unsigned)(v >> 32)); }

// ---------------------------------------------------------------------------
// Kernel 1: sparsemax over the last axis (D=6) of feature_selection_logits.
// ---------------------------------------------------------------------------
__global__ __launch_bounds__(256) void sparsemax_kernel(const float* __restrict__ fsl) {
    int idx = blockIdx.x * blockDim.x + threadIdx.x;   // 0 .. F_*T_-1
    if (idx >= F_ * T_) return;
    const float* zin = fsl + (size_t)idx * D_;
    float z[D_], zs[D_];
#pragma unroll
    for (int d = 0; d < D_; d++) { z[d] = zin[d]; zs[d] = z[d]; }
#pragma unroll
    for (int i = 0; i < D_; i++) {
#pragma unroll
        for (int j = 0; j < D_ - 1; j++) {
            if (zs[j] < zs[j + 1]) { float t = zs[j]; zs[j] = zs[j + 1]; zs[j + 1] = t; }
        }
    }
    float csum[D_];
    float cs = 0.0f;
#pragma unroll
    for (int k = 0; k < D_; k++) { cs += zs[k]; csum[k] = cs; }
    int kz = 0;
#pragma unroll
    for (int k = 0; k < D_; k++) {
        if (1.0f + (float)(k + 1) * zs[k] > csum[k]) kz++;
    }
    float tau = (csum[kz - 1] - 1.0f) / (float)kz;
    float* outp = g_sel + (size_t)idx * D_;
#pragma unroll
    for (int d = 0; d < D_; d++) outp[d] = fmaxf(z[d] - tau, 0.0f);
}

// ---------------------------------------------------------------------------
// Kernel 2: fused feature GEMM + sparsemoid + tree eval + response contraction.
// 512 threads, 32 batch rows/CTA. x transposed in smem (broadcast LDS.128),
// selector double-buffered with register-staged pipelining, response read
// straight from GMEM (L2-resident, warp-uniform __ldg).
// ---------------------------------------------------------------------------
__global__ __launch_bounds__(THREADS, 1) void odst_main(
    const float* __restrict__ x,
    const float* __restrict__ thr,
    const float* __restrict__ lt,
    const float* __restrict__ resp,
    float* __restrict__ out)
{
    extern __shared__ float smem[];
    float* x_t    = smem;                        // [256][XT_LD]     9216 f
    float* sel0   = x_t + 256 * XT_LD;           // [64][SEL_LD]    12544 f
    float* sel1   = sel0 + 64 * SEL_LD;          // [64][SEL_LD]    12544 f
    float* p_s    = sel1 + 64 * SEL_LD;          // [32][P_LD]       6304 f
    float* a_s    = p_s + 32 * P_LD;             // [192]
    float* b_s    = a_s + CCOLS;                 // [192]
    float* out_s  = b_s + CCOLS;                 // [32][16]          512 f

    const int tid  = threadIdx.x;
    const int row0 = blockIdx.x * BROWS;

    out_s[tid] = 0.0f;

    // ---- load x tile TRANSPOSED: x_t[c][row], c=0..255, row=0..31 ----
    {
        const int c   = tid & 255;
        const int r0t = (tid >> 8) * 16;     // 0 or 16
        float tmp[16];
#pragma unroll
        for (int i = 0; i < 16; i++)
            tmp[i] = __ldg(&x[(size_t)(row0 + r0t + i) * F_ + c]);
#pragma unroll
        for (int i = 0; i < 4; i++) {
            float4 v = make_float4(tmp[4 * i], tmp[4 * i + 1],
                                   tmp[4 * i + 2], tmp[4 * i + 3]);
            *(float4*)&x_t[c * XT_LD + r0t + i * 4] = v;
        }
    }

    // eval-phase decomposition: warp -> tree slot, lane -> (row quad, u quad)
    const int w    = tid >> 5;          // 0..15
    const int lane = tid & 31;
    const int rb   = (lane & 7) * 4;    // row base (4 rows)
    const int ub   = (lane >> 3) * 4;   // u base (4 outputs)

    // GEMM-phase decomposition: 8 row groups x 64 col groups, tile 4r x 3c
    const int colg = tid & 63;
    const int rowg = tid >> 6;          // 0..7
    const int c0   = colg * 3;
    const int r0g  = rowg * 4;

    // packed accumulators: pr pairs rows (rb+2pr, rb+2pr+1) in (lo, hi)
    u64 accp[2][4];
#pragma unroll
    for (int pr = 0; pr < 2; pr++)
#pragma unroll
        for (int uu = 0; uu < 4; uu++) accp[pr][uu] = 0ull;

    float* bufs[2] = { sel0, sel1 };

    for (int chunk = 0; chunk < NCHUNK; chunk++) {
        const int nbase = chunk * CCOLS;
        __syncthreads();  // prev chunk eval done (p_s, sel bufs free); x_t ready

        if (tid < CCOLS) {
            float e = 0.5f * expf(-lt[nbase + tid]);
            a_s[tid] = e;
            b_s[tid] = 0.5f - e * thr[nbase + tid];
        }

        // ---- stage kb=0 selector tile into buf0 ----
        {
            const float* gs = g_sel + nbase;   // kb = 0
            float4 st[6];
#pragma unroll
            for (int i = 0; i < 6; i++) {
                int q  = tid + i * 512;
                int kk = q / 48;
                int cc = (q % 48) * 4;
                st[i] = *(const float4*)&gs[kk * N_ + cc];
            }
#pragma unroll
            for (int i = 0; i < 6; i++) {
                int q  = tid + i * 512;
                int kk = q / 48;
                int cc = (q % 48) * 4;
                *(float4*)&sel0[kk * SEL_LD + cc] = st[i];
            }
        }
        __syncthreads();

        float fv[4][3];
#pragma unroll
        for (int i = 0; i < 4; i++) { fv[i][0] = 0.f; fv[i][1] = 0.f; fv[i][2] = 0.f; }

        for (int kb = 0; kb < 4; kb++) {
            const float* cur = bufs[kb & 1];
            float* nxt = bufs[(kb + 1) & 1];

            // prefetch next tile into registers (latency hidden by compute)
            float4 st[6];
            if (kb < 3) {
                const float* gs = g_sel + (size_t)((kb + 1) * 64) * N_ + nbase;
#pragma unroll
                for (int i = 0; i < 6; i++) {
                    int q  = tid + i * 512;
                    int kk = q / 48;
                    int cc = (q % 48) * 4;
                    st[i] = *(const float4*)&gs[kk * N_ + cc];
                }
            }

            // compute on current tile: 64 k-steps
            const float* xtk = x_t + (kb * 64) * XT_LD + r0g;
            const float* selc = cur + c0;
#pragma unroll 4
            for (int k = 0; k < 64; k++) {
                float4 xv = *(const float4*)(xtk + k * XT_LD);   // broadcast
                const float* sr = selc + k * SEL_LD;
                float s0 = sr[0], s1 = sr[1], s2 = sr[2];
                fv[0][0] = fmaf(xv.x, s0, fv[0][0]);
                fv[0][1] = fmaf(xv.x, s1, fv[0][1]);
                fv[0][2] = fmaf(xv.x, s2, fv[0][2]);
                fv[1][0] = fmaf(xv.y, s0, fv[1][0]);
                fv[1][1] = fmaf(xv.y, s1, fv[1][1]);
                fv[1][2] = fmaf(xv.y, s2, fv[1][2]);
                fv[2][0] = fmaf(xv.z, s0, fv[2][0]);
                fv[2][1] = fmaf(xv.z, s1, fv[2][1]);
                fv[2][2] = fmaf(xv.z, s2, fv[2][2]);
                fv[3][0] = fmaf(xv.w, s0, fv[3][0]);
                fv[3][1] = fmaf(xv.w, s1, fv[3][1]);
                fv[3][2] = fmaf(xv.w, s2, fv[3][2]);
            }

            if (kb < 3) {
#pragma unroll
                for (int i = 0; i < 6; i++) {
                    int q  = tid + i * 512;
                    int kk = q / 48;
                    int cc = (q % 48) * 4;
                    *(float4*)&nxt[kk * SEL_LD + cc] = st[i];
                }
                __syncthreads();
            }
        }

        // sparsemoid: p = saturate(a*fv + b)
#pragma unroll
        for (int i = 0; i < 4; i++) {
#pragma unroll
            for (int j = 0; j < 3; j++) {
                int cc = c0 + j;
                p_s[(r0g + i) * P_LD + cc] =
                    __saturatef(fmaf(a_s[cc], fv[i][j], b_s[cc]));
            }
        }
        __syncthreads();

        // ---- tree eval: warp w handles trees chunk*32 + {w, w+16} ----
        for (int it = 0; it < 2; it++) {
            const int tloc = it * 16 + w;
            const int tg   = chunk * 32 + tloc;
            const float4* rg = (const float4*)(resp + (size_t)tg * (U_ * NB_));

            const int pc = tloc * 6;
            // packed pairwise depth-product tables, rows paired (rb+2pr, rb+2pr+1)
            u64 r01p[2][4], r23p[2][4], r45p[2][4];
#pragma unroll
            for (int pr = 0; pr < 2; pr++) {
                const float* prow0 = p_s + (rb + 2 * pr) * P_LD + pc;
                const float* prow1 = prow0 + P_LD;
                u64 P0 = pk(prow0[0], prow1[0]);
                u64 P1 = pk(prow0[1], prow1[1]);
                u64 P2 = pk(prow0[2], prow1[2]);
                u64 P3 = pk(prow0[3], prow1[3]);
                u64 P4 = pk(prow0[4], prow1[4]);
                u64 P5 = pk(prow0[5], prow1[5]);
                const u64 ONE = 0x3f8000003f800000ull;
                const u64 NEG = 0xbf800000bf800000ull;
                u64 Q0 = fma2(P0, NEG, ONE);
                u64 Q1 = fma2(P1, NEG, ONE);
                u64 Q2 = fma2(P2, NEG, ONE);
                u64 Q3 = fma2(P3, NEG, ONE);
                u64 Q4 = fma2(P4, NEG, ONE);
                u64 Q5 = fma2(P5, NEG, ONE);
                r01p[pr][0] = mul2(P0, P1); r01p[pr][1] = mul2(Q0, P1);
                r01p[pr][2] = mul2(P0, Q1); r01p[pr][3] = mul2(Q0, Q1);
                r23p[pr][0] = mul2(P2, P3); r23p[pr][1] = mul2(Q2, P3);
                r23p[pr][2] = mul2(P2, Q3); r23p[pr][3] = mul2(Q2, Q3);
                r45p[pr][0] = mul2(P4, P5); r45p[pr][1] = mul2(Q4, P5);
                r45p[pr][2] = mul2(P4, Q5); r45p[pr][3] = mul2(Q4, Q5);
            }

#pragma unroll
            for (int j45 = 0; j45 < 4; j45++) {
#pragma unroll
                for (int j23 = 0; j23 < 4; j23++) {
                    u64 t2p0 = mul2(r45p[0][j45], r23p[0][j23]);
                    u64 t2p1 = mul2(r45p[1][j45], r23p[1][j23]);
                    const int cq = j45 * 4 + j23;       // float4 index of bin base
                    float4 rv0 = __ldg(&rg[(ub + 0) * 16 + cq]);
                    float4 rv1 = __ldg(&rg[(ub + 1) * 16 + cq]);
                    float4 rv2 = __ldg(&rg[(ub + 2) * 16 + cq]);
                    float4 rv3 = __ldg(&rg[(ub + 3) * 16 + cq]);
#pragma unroll
                    for (int j01 = 0; j01 < 4; j01++) {
                        u64 rw0 = mul2(t2p0, r01p[0][j01]);
                        u64 rw1 = mul2(t2p1, r01p[1][j01]);
                        u64 e0 = pkdup(f4get(rv0, j01));
                        u64 e1 = pkdup(f4get(rv1, j01));
                        u64 e2 = pkdup(f4get(rv2, j01));
                        u64 e3 = pkdup(f4get(rv3, j01));
                        accp[0][0] = fma2(rw0, e0, accp[0][0]);
                        accp[0][1] = fma2(rw0, e1, accp[0][1]);
                        accp[0][2] = fma2(rw0, e2, accp[0][2]);
                        accp[0][3] = fma2(rw0, e3, accp[0][3]);
                        accp[1][0] = fma2(rw1, e0, accp[1][0]);
                        accp[1][1] = fma2(rw1, e1, accp[1][1]);
                        accp[1][2] = fma2(rw1, e2, accp[1][2]);
                        accp[1][3] = fma2(rw1, e3, accp[1][3]);
                    }
                }
            }
        }
    }

    // unpack accumulators into scalars
    float acc[4][4];
#pragma unroll
    for (int pr = 0; pr < 2; pr++)
#pragma unroll
        for (int uu = 0; uu < 4; uu++) {
            acc[2 * pr + 0][uu] = lo32(accp[pr][uu]);
            acc[2 * pr + 1][uu] = hi32(accp[pr][uu]);
        }

    // deterministic cross-warp reduction into out_s
    for (int pass = 0; pass < 16; pass++) {
        __syncthreads();
        if (w == pass) {
#pragma unroll
            for (int rr = 0; rr < 4; rr++)
#pragma unroll
                for (int uu = 0; uu < 4; uu++)
                    out_s[(rb + rr) * U_ + ub + uu] += acc[rr][uu];
        }
    }
    __syncthreads();

    // write output: 32 rows x 16 u = 512 floats, one per thread (coalesced)
    out[(size_t)row0 * U_ + tid] = out_s[tid];
}

// ---------------------------------------------------------------------------
extern "C" void kernel_launch(void* const* d_in, const int* in_sizes, int n_in,
                              void* d_out, int out_size) {
    const float* x    = (const float*)d_in[0];
    const float* fsl  = (const float*)d_in[1];
    const float* thr  = (const float*)d_in[2];
    const float* lt   = (const float*)d_in[3];
    const float* resp = (const float*)d_in[4];
    float* out = (float*)d_out;

    const int smem_bytes =
        (256 * XT_LD + 2 * 64 * SEL_LD + 32 * P_LD + 2 * CCOLS + 512)
        * (int)sizeof(float);   // 166,016 B

    cudaFuncSetAttribute(odst_main, cudaFuncAttributeMaxDynamicSharedMemorySize,
                         smem_bytes);

    sparsemax_kernel<<<(F_ * T_) / 256, 256>>>(fsl);
    odst_main<<<(4096 / BROWS), THREADS, smem_bytes>>>(x, thr, lt, resp, out);
}